// round 1
// baseline (speedup 1.0000x reference)
#include <cuda_runtime.h>
#include <cstdint>

// Problem constants
#define NTOK 3136      // N = 56*56 tokens
#define CCH  96        // channels
#define BB   128       // batch
#define KF   49        // rfft bins = C/2+1
#define XS_STRIDE 132  // padded smem row stride (multiple of 4, not multiple of 32)

// Per-token real impulse responses h_n[d], d in [0,96). 1.2 MB scratch.
__device__ float g_H[NTOK * CCH];

// ---------------------------------------------------------------------------
// Kernel 1: h_n[d] = (1/96) * [ Re w0 + (-1)^d Re w48
//                               + 2 * sum_{k=1..47} (Re wk cos(2pi k d/96)
//                                                   - Im wk sin(2pi k d/96)) ]
// One block per token, 96 threads (one per d).
// ---------------------------------------------------------------------------
__global__ void compute_h_kernel(const float* __restrict__ w) {
    __shared__ float wr[KF], wi[KF];
    __shared__ float ct[CCH], st[CCH];
    const int n = blockIdx.x;
    const int d = threadIdx.x;  // 0..95

    if (d < KF) {
        wr[d] = w[(n * KF + d) * 2 + 0];
        wi[d] = w[(n * KF + d) * 2 + 1];
    }
    // Twiddle table for this block: e^{i 2pi d / 96}
    {
        float s, c;
        sincosf((float)d * (6.283185307179586f / 96.0f), &s, &c);
        ct[d] = c;
        st[d] = s;
    }
    __syncthreads();

    float acc = wr[0] + ((d & 1) ? -wr[48] : wr[48]);
    float sum = 0.0f;
#pragma unroll 4
    for (int k = 1; k < 48; k++) {
        int m = (k * d) % 96;
        sum = fmaf(wr[k], ct[m], sum);
        sum = fmaf(-wi[k], st[m], sum);
    }
    acc += 2.0f * sum;
    g_H[n * CCH + d] = acc * (1.0f / 96.0f);
}

// ---------------------------------------------------------------------------
// Kernel 2: per token n, y[b][c] = sum_j x[b][j] * h_n[(c-j) mod 96]
// Block = one token, all 128 batches. 256 threads, each owns an
// 8-batch x 6-channel tile held as 24 packed f32x2 accumulators.
// x is staged transposed in smem (xs[c][b], stride 132) so batch pairs load
// as LDS.128; h is duplicated (hd[192]) so the circulant index is mod-free.
// ---------------------------------------------------------------------------
extern __shared__ float smem_dyn[];

__device__ __forceinline__ void fma2(unsigned long long& d,
                                     unsigned long long a,
                                     unsigned long long b) {
    asm("fma.rn.f32x2 %0, %1, %2, %0;" : "+l"(d) : "l"(a), "l"(b));
}

__global__ void __launch_bounds__(256, 2)
conv_kernel(const float* __restrict__ x, float* __restrict__ out) {
    float* xs = smem_dyn;                       // [96][XS_STRIDE]
    float* hd = smem_dyn + CCH * XS_STRIDE;     // [192]

    const int n   = blockIdx.x;
    const int tid = threadIdx.x;
    const size_t NC = (size_t)NTOK * CCH;

    // Stage duplicated impulse response
    if (tid < CCH) {
        float hv = g_H[n * CCH + tid];
        hd[tid] = hv;
        hd[tid + CCH] = hv;
    }

    // Stage x transposed: xs[c][b] = x[b, n, c]. 128 rows * 24 float4 each.
    const size_t xoff = (size_t)n * CCH;
    for (int i = tid; i < BB * (CCH / 4); i += 256) {
        int b  = i / (CCH / 4);
        int c4 = i % (CCH / 4);
        float4 v = *(const float4*)(x + (size_t)b * NC + xoff + (size_t)(c4 * 4));
        int c = c4 * 4;
        xs[(c + 0) * XS_STRIDE + b] = v.x;
        xs[(c + 1) * XS_STRIDE + b] = v.y;
        xs[(c + 2) * XS_STRIDE + b] = v.z;
        xs[(c + 3) * XS_STRIDE + b] = v.w;
    }
    __syncthreads();

    const int tr = tid >> 4;       // 0..15 -> batch group
    const int tc = tid & 15;       // 0..15 -> channel group
    const int b0 = tr * 8;
    const int c0 = tc * 6;

    unsigned long long acc[4][6];
#pragma unroll
    for (int bp = 0; bp < 4; bp++)
#pragma unroll
        for (int cc = 0; cc < 6; cc++) acc[bp][cc] = 0ull;

    const float* hbase = hd + c0 + CCH;  // index (c0+96-j+cc) in [1,191]

#pragma unroll 4
    for (int j = 0; j < CCH; j++) {
        const float* xr = xs + j * XS_STRIDE + b0;
        ulonglong2 xv01 = *(const ulonglong2*)xr;        // (b0,b1),(b2,b3)
        ulonglong2 xv23 = *(const ulonglong2*)(xr + 4);  // (b4,b5),(b6,b7)
        unsigned long long xp[4] = {xv01.x, xv01.y, xv23.x, xv23.y};

        unsigned long long hp[6];
#pragma unroll
        for (int cc = 0; cc < 6; cc++) {
            unsigned hv = __float_as_uint(hbase[cc - j]);
            asm("mov.b64 %0, {%1, %1};" : "=l"(hp[cc]) : "r"(hv));
        }
#pragma unroll
        for (int bp = 0; bp < 4; bp++)
#pragma unroll
            for (int cc = 0; cc < 6; cc++) fma2(acc[bp][cc], xp[bp], hp[cc]);
    }

    // Write back: each accumulator pair = (batch even, batch odd)
#pragma unroll
    for (int bp = 0; bp < 4; bp++) {
        float* o0 = out + (size_t)(b0 + 2 * bp + 0) * NC + xoff + c0;
        float* o1 = out + (size_t)(b0 + 2 * bp + 1) * NC + xoff + c0;
#pragma unroll
        for (int cc = 0; cc < 6; cc++) {
            unsigned lo, hi;
            asm("mov.b64 {%0, %1}, %2;" : "=r"(lo), "=r"(hi) : "l"(acc[bp][cc]));
            o0[cc] = __uint_as_float(lo);
            o1[cc] = __uint_as_float(hi);
        }
    }
}

// ---------------------------------------------------------------------------
extern "C" void kernel_launch(void* const* d_in, const int* in_sizes, int n_in,
                              void* d_out, int out_size) {
    const float* x = (const float*)d_in[0];   // [B, N, C] float32
    const float* w = (const float*)d_in[1];   // [N, 49, 2] float32
    float* out = (float*)d_out;               // [B, N, C] float32

    compute_h_kernel<<<NTOK, CCH>>>(w);

    size_t smem = (size_t)(CCH * XS_STRIDE + 2 * CCH) * sizeof(float);  // 51456 B
    cudaFuncSetAttribute(conv_kernel,
                         cudaFuncAttributeMaxDynamicSharedMemorySize, (int)smem);
    conv_kernel<<<NTOK, 256, smem>>>(x, out);
}

// round 3
// speedup vs baseline: 1.8633x; 1.8633x over previous
#include <cuda_runtime.h>
#include <cuda_bf16.h>
#include <cstdint>

#define NTOK 3136
#define CCH  96
#define BB   128
#define KF   49
#define KS   104      // padded K stride in bf16 elements
#define KSB  208      // = KS * 2 bytes

// ---- smem layout (bytes) ----
#define SM_WR   0                      // 49 f32
#define SM_WI   256                    // 49 f32
#define SM_CT   512                    // 96 f32
#define SM_ST   896                    // 96 f32
#define SM_HHI  1280                   // 96 u16
#define SM_HLO  1472                   // 96 u16
#define SM_XH   1792                   // 128 x 104 bf16 (26624 B)
#define SM_XL   (SM_XH + BB * KSB)     // 28416
#define SM_BH   (SM_XL + BB * KSB)     // 55040: 96 x 104 bf16
#define SM_BL   (SM_BH + CCH * KSB)    // 75008
#define SMEM_BYTES (SM_BL + CCH * KSB) // 94976

__device__ __forceinline__ uint32_t smem_u32(const void* p) {
    uint32_t a;
    asm("{ .reg .u64 t; cvta.to.shared.u64 t, %1; cvt.u32.u64 %0, t; }"
        : "=r"(a) : "l"(p));
    return a;
}

__device__ __forceinline__ void ldsm_x4(uint32_t* r, uint32_t addr) {
    asm volatile("ldmatrix.sync.aligned.m8n8.x4.shared.b16 {%0,%1,%2,%3}, [%4];"
                 : "=r"(r[0]), "=r"(r[1]), "=r"(r[2]), "=r"(r[3]) : "r"(addr));
}

__device__ __forceinline__ void mma_bf16(float* c, const uint32_t* a,
                                         uint32_t b0, uint32_t b1) {
    asm volatile(
        "mma.sync.aligned.m16n8k16.row.col.f32.bf16.bf16.f32 "
        "{%0,%1,%2,%3}, {%4,%5,%6,%7}, {%8,%9}, {%0,%1,%2,%3};"
        : "+f"(c[0]), "+f"(c[1]), "+f"(c[2]), "+f"(c[3])
        : "r"(a[0]), "r"(a[1]), "r"(a[2]), "r"(a[3]), "r"(b0), "r"(b1));
}

__device__ __forceinline__ uint32_t pack_bf2(__nv_bfloat16 a, __nv_bfloat16 b) {
    return (uint32_t)__bfloat16_as_ushort(a) | ((uint32_t)__bfloat16_as_ushort(b) << 16);
}

extern __shared__ unsigned char smem_raw[];

__global__ void __launch_bounds__(256, 2)
gf_hmma_kernel(const float* __restrict__ x, const float* __restrict__ w,
               float* __restrict__ out) {
    const int tid  = threadIdx.x;
    const int n    = blockIdx.x;
    const size_t NC   = (size_t)NTOK * CCH;
    const size_t xoff = (size_t)n * CCH;

    float* wr = (float*)(smem_raw + SM_WR);
    float* wi = (float*)(smem_raw + SM_WI);
    float* ct = (float*)(smem_raw + SM_CT);
    float* st = (float*)(smem_raw + SM_ST);
    unsigned short* hhi = (unsigned short*)(smem_raw + SM_HHI);
    unsigned short* hlo = (unsigned short*)(smem_raw + SM_HLO);

    // ---- phase 1: load filter coeffs + twiddles; stage X -> bf16 hi/lo ----
    if (tid < KF) {
        wr[tid] = w[((size_t)n * KF + tid) * 2 + 0];
        wi[tid] = w[((size_t)n * KF + tid) * 2 + 1];
    }
    if (tid < CCH) {
        float s, c;
        sincosf((float)tid * (6.283185307179586f / 96.0f), &s, &c);
        ct[tid] = c;
        st[tid] = s;
    }

    // X staging: 128 rows x 24 float4 each
#pragma unroll 2
    for (int idx = tid; idx < BB * 24; idx += 256) {
        int row = idx / 24;
        int c4  = idx % 24;
        float4 v = *(const float4*)(x + (size_t)row * NC + xoff + (size_t)(c4 * 4));
        __nv_bfloat16 h0 = __float2bfloat16(v.x);
        __nv_bfloat16 h1 = __float2bfloat16(v.y);
        __nv_bfloat16 h2 = __float2bfloat16(v.z);
        __nv_bfloat16 h3 = __float2bfloat16(v.w);
        __nv_bfloat16 l0 = __float2bfloat16(v.x - __bfloat162float(h0));
        __nv_bfloat16 l1 = __float2bfloat16(v.y - __bfloat162float(h1));
        __nv_bfloat16 l2 = __float2bfloat16(v.z - __bfloat162float(h2));
        __nv_bfloat16 l3 = __float2bfloat16(v.w - __bfloat162float(h3));
        uint32_t off = (uint32_t)(row * KSB + c4 * 8);
        *(uint32_t*)(smem_raw + SM_XH + off)     = pack_bf2(h0, h1);
        *(uint32_t*)(smem_raw + SM_XH + off + 4) = pack_bf2(h2, h3);
        *(uint32_t*)(smem_raw + SM_XL + off)     = pack_bf2(l0, l1);
        *(uint32_t*)(smem_raw + SM_XL + off + 4) = pack_bf2(l2, l3);
    }
    __syncthreads();

    // ---- phase 2: h[d] via DFT (validated in R1) ----
    if (tid < CCH) {
        const int d = tid;
        float acc = wr[0] + ((d & 1) ? -wr[48] : wr[48]);
        float sum = 0.0f;
#pragma unroll 4
        for (int k = 1; k < 48; k++) {
            int m = (k * d) % 96;
            sum = fmaf(wr[k], ct[m], sum);
            sum = fmaf(-wi[k], st[m], sum);
        }
        float hv = (acc + 2.0f * sum) * (1.0f / 96.0f);
        __nv_bfloat16 hh = __float2bfloat16(hv);
        float rem = hv - __bfloat162float(hh);
        hhi[d] = __bfloat16_as_ushort(hh);
        hlo[d] = __bfloat16_as_ushort(__float2bfloat16(rem));
    }
    __syncthreads();

    // ---- phase 3: build circulant B[nrow][k] = h[(nrow - k) mod 96] ----
    // 96 rows x 48 u32 pairs
    for (int idx = tid; idx < CCH * 48; idx += 256) {
        int row = idx / 48;
        int p   = idx % 48;
        int m0 = row - 2 * p; if (m0 < 0) m0 += CCH;
        int m1 = m0 - 1;      if (m1 < 0) m1 += CCH;
        uint32_t vh = (uint32_t)hhi[m0] | ((uint32_t)hhi[m1] << 16);
        uint32_t vl = (uint32_t)hlo[m0] | ((uint32_t)hlo[m1] << 16);
        uint32_t off = (uint32_t)(row * KSB + p * 4);
        *(uint32_t*)(smem_raw + SM_BH + off) = vh;
        *(uint32_t*)(smem_raw + SM_BL + off) = vl;
    }
    __syncthreads();

    // ---- phase 4: MMA. warp w owns m-rows [w*16, w*16+16) ----
    const int wid  = tid >> 5;
    const int lane = tid & 31;
    const int m0   = wid * 16;

    const uint32_t base   = smem_u32(smem_raw);
    const int lrow  = lane & 15;           // addressed row within 16-row tile
    const int lhalf = (lane >> 4) << 4;    // 0 or 16 bytes (k halves)

    const uint32_t a_h = base + SM_XH + (uint32_t)((m0 + lrow) * KSB) + lhalf;
    const uint32_t a_l = base + SM_XL + (uint32_t)((m0 + lrow) * KSB) + lhalf;
    const uint32_t b_h = base + SM_BH + (uint32_t)(lrow * KSB) + lhalf;
    const uint32_t b_l = base + SM_BL + (uint32_t)(lrow * KSB) + lhalf;

    float acc[12][4];
#pragma unroll
    for (int t = 0; t < 12; t++)
#pragma unroll
        for (int q = 0; q < 4; q++) acc[t][q] = 0.0f;

#pragma unroll
    for (int ks = 0; ks < 6; ks++) {
        const uint32_t koff = (uint32_t)(ks * 32);  // 16 bf16 = 32 B per k-step
        uint32_t ah[4], al[4];
        ldsm_x4(ah, a_h + koff);
        ldsm_x4(al, a_l + koff);
#pragma unroll
        for (int nt2 = 0; nt2 < 6; nt2++) {
            const uint32_t noff = (uint32_t)(nt2 * 16 * KSB) + koff;
            uint32_t bh[4], bl[4];
            ldsm_x4(bh, b_h + noff);
            ldsm_x4(bl, b_l + noff);
            // ntile 2*nt2: frag {r0, r2}; ntile 2*nt2+1: frag {r1, r3}
            mma_bf16(acc[2 * nt2],     ah, bh[0], bh[2]);
            mma_bf16(acc[2 * nt2],     ah, bl[0], bl[2]);
            mma_bf16(acc[2 * nt2],     al, bh[0], bh[2]);
            mma_bf16(acc[2 * nt2 + 1], ah, bh[1], bh[3]);
            mma_bf16(acc[2 * nt2 + 1], ah, bl[1], bl[3]);
            mma_bf16(acc[2 * nt2 + 1], al, bh[1], bh[3]);
        }
    }

    // ---- phase 5: epilogue. c0,c1 -> row m0+lane/4; c2,c3 -> +8 ----
    const int r0 = m0 + (lane >> 2);
    const int cb = (lane & 3) * 2;
    float* o0 = out + (size_t)r0 * NC + xoff;
    float* o1 = out + (size_t)(r0 + 8) * NC + xoff;
#pragma unroll
    for (int t = 0; t < 12; t++) {
        const int col = t * 8 + cb;
        *(float2*)(o0 + col) = make_float2(acc[t][0], acc[t][1]);
        *(float2*)(o1 + col) = make_float2(acc[t][2], acc[t][3]);
    }
}

// ---------------------------------------------------------------------------
extern "C" void kernel_launch(void* const* d_in, const int* in_sizes, int n_in,
                              void* d_out, int out_size) {
    const float* x = (const float*)d_in[0];   // [B, N, C] f32
    const float* w = (const float*)d_in[1];   // [N, 49, 2] f32
    float* out = (float*)d_out;

    cudaFuncSetAttribute(gf_hmma_kernel,
                         cudaFuncAttributeMaxDynamicSharedMemorySize, SMEM_BYTES);
    gf_hmma_kernel<<<NTOK, 256, SMEM_BYTES>>>(x, w, out);
}

// round 5
// speedup vs baseline: 2.6890x; 1.4432x over previous
#include <cuda_runtime.h>
#include <cuda_fp16.h>
#include <cstdint>

#define NTOK 3136
#define CCH  96
#define BB   128
#define KF   49
#define KSB  208   // smem row stride in bytes (13*16 -> conflict-free ldmatrix)

// fp16 impulse responses, one per (token, d). 602 KB scratch.
__device__ unsigned short g_H[NTOK * CCH];

// ---------------- main-kernel smem layout (bytes), total 73472 ----------------
#define SM_HH  0                        // 96 u16
#define SM_XH  256                      // 128 x 208 B = 26624
#define SM_XL  (SM_XH + BB * KSB)       // 26880
#define SM_BH  (SM_XL + BB * KSB)       // 53504: 96 x 208 B
#define SMEM_BYTES (SM_BH + CCH * KSB)  // 73472

__device__ __forceinline__ uint32_t smem_u32(const void* p) {
    uint32_t a;
    asm("{ .reg .u64 t; cvta.to.shared.u64 t, %1; cvt.u32.u64 %0, t; }"
        : "=r"(a) : "l"(p));
    return a;
}
__device__ __forceinline__ void ldsm_x4(uint32_t* r, uint32_t addr) {
    asm volatile("ldmatrix.sync.aligned.m8n8.x4.shared.b16 {%0,%1,%2,%3}, [%4];"
                 : "=r"(r[0]), "=r"(r[1]), "=r"(r[2]), "=r"(r[3]) : "r"(addr));
}
__device__ __forceinline__ void mma_fp16(float* c, const uint32_t* a,
                                         uint32_t b0, uint32_t b1) {
    asm volatile(
        "mma.sync.aligned.m16n8k16.row.col.f32.f16.f16.f32 "
        "{%0,%1,%2,%3}, {%4,%5,%6,%7}, {%8,%9}, {%0,%1,%2,%3};"
        : "+f"(c[0]), "+f"(c[1]), "+f"(c[2]), "+f"(c[3])
        : "r"(a[0]), "r"(a[1]), "r"(a[2]), "r"(a[3]), "r"(b0), "r"(b1));
}

// ---------------------------------------------------------------------------
// Kernel 1: DFT of w -> fp16 impulse response h. 4 tokens per 384-thread block.
// h[d] = (1/96)[Re w0 + (-1)^d Re w48 + 2*sum_{k=1..47}(Re wk cos - Im wk sin)]
// ---------------------------------------------------------------------------
__global__ void __launch_bounds__(384)
compute_h_kernel(const float* __restrict__ w) {
    __shared__ float wc[4 * 98];        // 4 tokens x 49 bins x (re,im)
    __shared__ float ct[CCH], st[CCH];
    const int t = threadIdx.x;

    for (int i = t; i < 4 * 98; i += 384)           // FIX: 392 > blockDim
        wc[i] = w[(size_t)blockIdx.x * 392 + i];
    if (t < CCH) {
        float s, c;
        sincosf((float)t * (6.283185307179586f / 96.0f), &s, &c);
        ct[t] = c;
        st[t] = s;
    }
    __syncthreads();

    const int tok = t / CCH;            // 0..3
    const int d   = t - tok * CCH;      // 0..95
    const float* wp = wc + tok * 98;    // wp[2k]=re, wp[2k+1]=im

    float acc = wp[0] + ((d & 1) ? -wp[96] : wp[96]);
    float sum = 0.0f;
    int m = 0;
#pragma unroll 4
    for (int k = 1; k < 48; k++) {
        m += d; if (m >= CCH) m -= CCH;
        sum = fmaf(wp[2 * k], ct[m], sum);
        sum = fmaf(-wp[2 * k + 1], st[m], sum);
    }
    float hv = (acc + 2.0f * sum) * (1.0f / 96.0f);
    g_H[(size_t)(blockIdx.x * 4 + tok) * CCH + d] = __half_as_ushort(__float2half_rn(hv));
}

// ---------------------------------------------------------------------------
// Kernel 2: per token n, Y[128,96] = (Xh + Xl)[128,96] * B[96,96]^T
// with B[row][k] = h[(row-k) mod 96], all fp16, fp32 accum (2 MMA products).
// ---------------------------------------------------------------------------
extern __shared__ unsigned char smem_raw[];

__global__ void __launch_bounds__(256, 3)
gf_hmma_kernel(const float* __restrict__ x, float* __restrict__ out) {
    const int tid = threadIdx.x;
    const int n   = blockIdx.x;
    const size_t NC   = (size_t)NTOK * CCH;
    const size_t xoff = (size_t)n * CCH;

    unsigned short* hh = (unsigned short*)(smem_raw + SM_HH);

    // ---- phase 1: load h; stage X -> fp16 hi/lo in smem ----
    if (tid < CCH) hh[tid] = g_H[(size_t)n * CCH + tid];

#pragma unroll
    for (int batch = 0; batch < 2; batch++) {
        float4 v[6];
        int idxs[6];
#pragma unroll
        for (int i = 0; i < 6; i++) {
            int idx = tid + (batch * 6 + i) * 256;       // 0..3071
            idxs[i] = idx;
            int row = idx / 24, c4 = idx % 24;
            v[i] = *(const float4*)(x + (size_t)row * NC + xoff + (size_t)(c4 * 4));
        }
#pragma unroll
        for (int i = 0; i < 6; i++) {
            int row = idxs[i] / 24, c4 = idxs[i] % 24;
            __half h0 = __float2half_rn(v[i].x);
            __half h1 = __float2half_rn(v[i].y);
            __half h2 = __float2half_rn(v[i].z);
            __half h3 = __float2half_rn(v[i].w);
            __half l0 = __float2half_rn(v[i].x - __half2float(h0));
            __half l1 = __float2half_rn(v[i].y - __half2float(h1));
            __half l2 = __float2half_rn(v[i].z - __half2float(h2));
            __half l3 = __float2half_rn(v[i].w - __half2float(h3));
            uint32_t off = (uint32_t)(row * KSB + c4 * 8);
            *(uint32_t*)(smem_raw + SM_XH + off)     =
                (uint32_t)__half_as_ushort(h0) | ((uint32_t)__half_as_ushort(h1) << 16);
            *(uint32_t*)(smem_raw + SM_XH + off + 4) =
                (uint32_t)__half_as_ushort(h2) | ((uint32_t)__half_as_ushort(h3) << 16);
            *(uint32_t*)(smem_raw + SM_XL + off)     =
                (uint32_t)__half_as_ushort(l0) | ((uint32_t)__half_as_ushort(l1) << 16);
            *(uint32_t*)(smem_raw + SM_XL + off + 4) =
                (uint32_t)__half_as_ushort(l2) | ((uint32_t)__half_as_ushort(l3) << 16);
        }
    }
    __syncthreads();

    // ---- phase 2: build circulant B[row][k] = h[(row-k) mod 96] ----
#pragma unroll 2
    for (int i = tid; i < CCH * 48; i += 256) {
        int row = i / 48;
        int p   = i - row * 48;                 // u32 pair index (k = 2p, 2p+1)
        int m0 = row - 2 * p; if (m0 < 0) m0 += CCH;
        int m1 = m0 - 1;      if (m1 < 0) m1 += CCH;
        uint32_t vh = (uint32_t)hh[m0] | ((uint32_t)hh[m1] << 16);
        *(uint32_t*)(smem_raw + SM_BH + (uint32_t)(row * KSB + p * 4)) = vh;
    }
    __syncthreads();

    // ---- phase 3: MMA. warp tile = 32 rows x 48 cols ----
    const int wid  = tid >> 5;
    const int lane = tid & 31;
    const int m0   = (wid & 3) * 32;
    const int n0   = (wid >> 2) * 48;

    const uint32_t base  = smem_u32(smem_raw);
    const int lrow  = lane & 15;
    const int lhalf = (lane >> 4) << 4;

    const uint32_t a_h = base + SM_XH + (uint32_t)((m0 + lrow) * KSB) + lhalf;
    const uint32_t a_l = base + SM_XL + (uint32_t)((m0 + lrow) * KSB) + lhalf;
    const uint32_t b_b = base + SM_BH + (uint32_t)((n0 + lrow) * KSB) + lhalf;

    float acc[2][6][4];
#pragma unroll
    for (int mt = 0; mt < 2; mt++)
#pragma unroll
        for (int nt = 0; nt < 6; nt++)
#pragma unroll
            for (int q = 0; q < 4; q++) acc[mt][nt][q] = 0.0f;

#pragma unroll
    for (int ks = 0; ks < 6; ks++) {
        const uint32_t koff = (uint32_t)(ks * 32);
        uint32_t ah0[4], ah1[4], al0[4], al1[4];
        ldsm_x4(ah0, a_h + koff);
        ldsm_x4(ah1, a_h + koff + 16 * KSB);
        ldsm_x4(al0, a_l + koff);
        ldsm_x4(al1, a_l + koff + 16 * KSB);
        uint32_t b0[4], b1[4], b2[4];
        ldsm_x4(b0, b_b + koff);
        ldsm_x4(b1, b_b + koff + 16 * KSB);
        ldsm_x4(b2, b_b + koff + 32 * KSB);

        // n8 tile nt: fragment = {bX[0],bX[2]} (even) / {bX[1],bX[3]} (odd)
        mma_fp16(acc[0][0], ah0, b0[0], b0[2]);
        mma_fp16(acc[0][1], ah0, b0[1], b0[3]);
        mma_fp16(acc[0][2], ah0, b1[0], b1[2]);
        mma_fp16(acc[0][3], ah0, b1[1], b1[3]);
        mma_fp16(acc[0][4], ah0, b2[0], b2[2]);
        mma_fp16(acc[0][5], ah0, b2[1], b2[3]);
        mma_fp16(acc[1][0], ah1, b0[0], b0[2]);
        mma_fp16(acc[1][1], ah1, b0[1], b0[3]);
        mma_fp16(acc[1][2], ah1, b1[0], b1[2]);
        mma_fp16(acc[1][3], ah1, b1[1], b1[3]);
        mma_fp16(acc[1][4], ah1, b2[0], b2[2]);
        mma_fp16(acc[1][5], ah1, b2[1], b2[3]);
        mma_fp16(acc[0][0], al0, b0[0], b0[2]);
        mma_fp16(acc[0][1], al0, b0[1], b0[3]);
        mma_fp16(acc[0][2], al0, b1[0], b1[2]);
        mma_fp16(acc[0][3], al0, b1[1], b1[3]);
        mma_fp16(acc[0][4], al0, b2[0], b2[2]);
        mma_fp16(acc[0][5], al0, b2[1], b2[3]);
        mma_fp16(acc[1][0], al1, b0[0], b0[2]);
        mma_fp16(acc[1][1], al1, b0[1], b0[3]);
        mma_fp16(acc[1][2], al1, b1[0], b1[2]);
        mma_fp16(acc[1][3], al1, b1[1], b1[3]);
        mma_fp16(acc[1][4], al1, b2[0], b2[2]);
        mma_fp16(acc[1][5], al1, b2[1], b2[3]);
    }

    // ---- phase 4: epilogue ----
    const int rbase = m0 + (lane >> 2);
    const int cb    = n0 + (lane & 3) * 2;
#pragma unroll
    for (int mt = 0; mt < 2; mt++) {
        float* o0 = out + (size_t)(rbase + mt * 16) * NC + xoff;
        float* o1 = o0 + 8 * NC;
#pragma unroll
        for (int nt = 0; nt < 6; nt++) {
            const int col = cb + nt * 8;
            *(float2*)(o0 + col) = make_float2(acc[mt][nt][0], acc[mt][nt][1]);
            *(float2*)(o1 + col) = make_float2(acc[mt][nt][2], acc[mt][nt][3]);
        }
    }
}

// ---------------------------------------------------------------------------
extern "C" void kernel_launch(void* const* d_in, const int* in_sizes, int n_in,
                              void* d_out, int out_size) {
    const float* x = (const float*)d_in[0];   // [B, N, C] f32
    const float* w = (const float*)d_in[1];   // [N, 49, 2] f32
    float* out = (float*)d_out;

    compute_h_kernel<<<NTOK / 4, 384>>>(w);

    cudaFuncSetAttribute(gf_hmma_kernel,
                         cudaFuncAttributeMaxDynamicSharedMemorySize, SMEM_BYTES);
    gf_hmma_kernel<<<NTOK, 256, SMEM_BYTES>>>(x, out);
}